// round 2
// baseline (speedup 1.0000x reference)
#include <cuda_runtime.h>

// T=4 LIF over repeated input.
// in:  (B=32, L=720, C=862) f32
// out: (T=4, B=32, C=862, L=720) f32 spikes
// Per element: v=0; 4x { v=(v+x)/2; s=(v>=1); if(s) v=0; }  -> elementwise + transpose.
// HBM-bound: 79.4MB read + 317.8MB write.
//
// R2: 128(L)x32(C) tiles. Each warp stores one contiguous 512B run per
// (plane, c-row). Rotate-swizzled smem (col = (c + (l>>2)) & 31) is
// conflict-free in both phases with zero padding. __ldcs/__stcs streaming
// (read-once / write-once data, keep L2 clean).

#define L_DIM 720
#define C_DIM 862
#define B_DIM 32
#define T_STEPS 4
#define TILE_L 128
#define TILE_C 32

__global__ __launch_bounds__(256, 8)
void lif_transpose_kernel(const float* __restrict__ in, float* __restrict__ out) {
    __shared__ float tile[TILE_L][TILE_C];   // swizzled: [l][(c + (l>>2)) & 31]

    const int b     = blockIdx.z;
    const int lBase = blockIdx.y * TILE_L;
    const int cBase = blockIdx.x * TILE_C;
    const int tx = threadIdx.x;   // 0..31 (C lane in load phase)
    const int ty = threadIdx.y;   // 0..7

    // ---- load: coalesced along C; swizzled STS (conflict-free: col = tx + const) ----
    const float* inb = in + (size_t)b * ((size_t)L_DIM * C_DIM);
    const int c_in = cBase + tx;
    if (c_in < C_DIM) {
#pragma unroll
        for (int k = 0; k < TILE_L / 8; k++) {
            int ll = ty + k * 8;
            int l  = lBase + ll;
            if (l < L_DIM)
                tile[ll][(tx + (ll >> 2)) & 31] = __ldcs(inb + (size_t)l * C_DIM + c_in);
        }
    }
    __syncthreads();

    // ---- write: warp w handles c-rows {4w..4w+3}; each lane owns 4 consecutive l
    //      -> one 512B contiguous store per (warp, row, plane). ----
    const int tid  = ty * 32 + tx;
    const int w    = tid >> 5;     // 0..7
    const int lane = tid & 31;
    const int l_local = lane * 4;
    const int l = lBase + l_local;
    if (l >= L_DIM) return;        // L_DIM % 4 == 0: float4 fully valid or fully out

    const size_t plane = (size_t)B_DIM * C_DIM * L_DIM;
    float* ob = out + (size_t)b * ((size_t)C_DIM * L_DIM) + l;

#pragma unroll
    for (int it = 0; it < 4; it++) {
        const int c_local = w * 4 + it;
        const int c = cBase + c_local;
        if (c >= C_DIM) continue;

        float sv[T_STEPS][4];
#pragma unroll
        for (int j = 0; j < 4; j++) {
            // LDS bank = (c_local + lane) & 31 -> permutation over lanes: conflict-free
            float x = tile[l_local + j][(c_local + lane) & 31];
            float v = 0.0f;
#pragma unroll
            for (int t = 0; t < T_STEPS; t++) {
                v = (v + x) * 0.5f;
                bool fire = (v >= 1.0f);
                sv[t][j] = fire ? 1.0f : 0.0f;
                v = fire ? 0.0f : v;
            }
        }

        float* orow = ob + (size_t)c * L_DIM;
#pragma unroll
        for (int t = 0; t < T_STEPS; t++) {
            float4 v4 = make_float4(sv[t][0], sv[t][1], sv[t][2], sv[t][3]);
            __stcs(reinterpret_cast<float4*>(orow + t * plane), v4);
        }
    }
}

extern "C" void kernel_launch(void* const* d_in, const int* in_sizes, int n_in,
                              void* d_out, int out_size) {
    const float* in = (const float*)d_in[0];
    float* out = (float*)d_out;
    dim3 block(32, 8);
    dim3 grid((C_DIM + TILE_C - 1) / TILE_C,   // 27
              (L_DIM + TILE_L - 1) / TILE_L,   // 6
              B_DIM);                          // 32
    lif_transpose_kernel<<<grid, block>>>(in, out);
}

// round 3
// speedup vs baseline: 1.0398x; 1.0398x over previous
#include <cuda_runtime.h>

// T=4 LIF over repeated input.
// in:  (B=32, L=720, C=862) f32
// out: (T=4, B=32, C=862, L=720) f32 spikes
// Per element: v=0; 4x { v=(v+x)/2; s=(v>=1); if(s) v=0; }
// HBM-bound: 79.4MB read + 317.8MB write = 397.2MB min traffic.
//
// R3 = R1 structure (32x32 tile, 19872 blocks — best so far) + __stcs on the
// write-once output stream (evict-first, keep L2 for the in-flight read mix).

#define L_DIM 720
#define C_DIM 862
#define B_DIM 32
#define T_STEPS 4
#define TILE 32

__global__ __launch_bounds__(256, 8)
void lif_transpose_kernel(const float* __restrict__ in, float* __restrict__ out) {
    __shared__ float tile[TILE][TILE + 1];

    const int b     = blockIdx.z;
    const int lBase = blockIdx.y * TILE;
    const int cBase = blockIdx.x * TILE;
    const int tx = threadIdx.x;   // 0..31
    const int ty = threadIdx.y;   // 0..7

    // ---- load phase: coalesced along C (input-contiguous) ----
    const float* inb = in + (size_t)b * ((size_t)L_DIM * C_DIM);
    const int c_in = cBase + tx;
    if (c_in < C_DIM) {
#pragma unroll
        for (int k = 0; k < 4; k++) {
            int l = lBase + ty + k * 8;
            if (l < L_DIM)
                tile[ty + k * 8][tx] = inb[(size_t)l * C_DIM + c_in];
        }
    }
    __syncthreads();

    // ---- write phase: each thread owns (1 c, 4 consecutive l) -> float4 along L ----
    const int tid     = ty * 32 + tx;
    const int c_local = tid >> 3;      // 0..31
    const int l4      = tid & 7;       // 0..7
    const int c = cBase + c_local;
    const int l = lBase + l4 * 4;
    // L_DIM % 4 == 0, lBase % 32 == 0 -> each float4 fully valid or fully OOB.
    if (c >= C_DIM || l >= L_DIM) return;

    float sv[T_STEPS][4];
#pragma unroll
    for (int j = 0; j < 4; j++) {
        float x = tile[l4 * 4 + j][c_local];
        float v = 0.0f;
#pragma unroll
        for (int t = 0; t < T_STEPS; t++) {
            v = (v + x) * 0.5f;
            bool fire = (v >= 1.0f);
            sv[t][j] = fire ? 1.0f : 0.0f;
            v = fire ? 0.0f : v;
        }
    }

    const size_t plane = (size_t)B_DIM * C_DIM * L_DIM;
    float* obase = out + (size_t)b * ((size_t)C_DIM * L_DIM) + (size_t)c * L_DIM + l;
#pragma unroll
    for (int t = 0; t < T_STEPS; t++) {
        float4 v4 = make_float4(sv[t][0], sv[t][1], sv[t][2], sv[t][3]);
        __stcs(reinterpret_cast<float4*>(obase + t * plane), v4);
    }
}

extern "C" void kernel_launch(void* const* d_in, const int* in_sizes, int n_in,
                              void* d_out, int out_size) {
    const float* in = (const float*)d_in[0];
    float* out = (float*)d_out;
    dim3 block(32, 8);
    dim3 grid((C_DIM + TILE - 1) / TILE,   // 27
              (L_DIM + TILE - 1) / TILE,   // 23
              B_DIM);                      // 32
    lif_transpose_kernel<<<grid, block>>>(in, out);
}